// round 1
// baseline (speedup 1.0000x reference)
#include <cuda_runtime.h>
#include <math.h>

#define N_NODES 50000
#define H 8
#define D 32
#define DEG 16
#define HD (H * D)   // 256
#define NH (N_NODES * H)

// Scratch for precomputed attention dot-products (no cudaMalloc allowed).
__device__ float g_el[NH];
__device__ float g_er[NH];

// ---------------------------------------------------------------------------
// Kernel 1: el[n,h] = sum_d feat[n,h,d]*attn_l[h,d]; er likewise (one pass).
// ---------------------------------------------------------------------------
__global__ void precompute_dots(const float* __restrict__ feat,
                                const float* __restrict__ attn_l,
                                const float* __restrict__ attn_r) {
    __shared__ __align__(16) float sal[HD];
    __shared__ __align__(16) float sar[HD];
    int t = threadIdx.x;
    sal[t] = attn_l[t];
    sar[t] = attn_r[t];
    __syncthreads();

    int idx = blockIdx.x * blockDim.x + t;
    if (idx >= NH) return;
    int n = idx >> 3;       // node
    int h = idx & 7;        // head

    const float4* f  = reinterpret_cast<const float4*>(feat + (size_t)n * HD + h * D);
    const float4* al = reinterpret_cast<const float4*>(sal + h * D);
    const float4* ar = reinterpret_cast<const float4*>(sar + h * D);

    float sl = 0.f, sr = 0.f;
#pragma unroll
    for (int i = 0; i < D / 4; i++) {
        float4 v = f[i];
        float4 a = al[i];
        float4 b = ar[i];
        sl += v.x * a.x + v.y * a.y + v.z * a.z + v.w * a.w;
        sr += v.x * b.x + v.y * b.y + v.z * b.z + v.w * b.w;
    }
    g_el[idx] = sl;
    g_er[idx] = sr;
}

// ---------------------------------------------------------------------------
// Kernel 2: one block (256 threads) per destination node.
// Edges for node n are [16n, 16n+16) because dst = repeat(arange(N), 16).
// ---------------------------------------------------------------------------
__global__ __launch_bounds__(256) void gat_aggregate(
        const float* __restrict__ feat,
        const float* __restrict__ bias,
        const int*   __restrict__ src,
        float* __restrict__ out) {
    int n = blockIdx.x;
    int t = threadIdx.x;

    __shared__ int   s_src[DEG];
    __shared__ float s_er[H];
    __shared__ float s_e[DEG][H];
    __shared__ float s_a[DEG][H];

    if (t < DEG)            s_src[t]      = src[n * DEG + t];
    if (t >= 32 && t < 40)  s_er[t - 32]  = g_er[n * H + (t - 32)];
    __syncthreads();

    // 128 threads compute the 16x8 logits
    if (t < DEG * H) {
        int j = t >> 3;      // edge slot
        int h = t & 7;       // head
        float e = g_el[s_src[j] * H + h] + s_er[h];
        e = (e > 0.f) ? e : 0.2f * e;   // leaky relu
        s_e[j][h] = e;
    }
    __syncthreads();

    // 8 threads: per-head softmax over the 16 incoming edges
    if (t < H) {
        float m = -INFINITY;
#pragma unroll
        for (int j = 0; j < DEG; j++) m = fmaxf(m, s_e[j][t]);
        float sum = 0.f;
#pragma unroll
        for (int j = 0; j < DEG; j++) {
            float ex = __expf(s_e[j][t] - m);
            s_a[j][t] = ex;
            sum += ex;
        }
        float inv = 1.f / sum;
#pragma unroll
        for (int j = 0; j < DEG; j++) s_a[j][t] *= inv;
    }
    __syncthreads();

    // Weighted gather-aggregate: thread t handles (h, d).
    int h = t >> 5;
    int d = t & 31;
    float acc = bias[t];
#pragma unroll
    for (int j = 0; j < DEG; j++) {
        // all 32 lanes of a warp share (s_src[j], h) -> coalesced 128B load
        acc += s_a[j][h] * feat[(size_t)s_src[j] * HD + h * D + d];
    }
    out[(size_t)n * HD + t] = acc;
}

// ---------------------------------------------------------------------------
extern "C" void kernel_launch(void* const* d_in, const int* in_sizes, int n_in,
                              void* d_out, int out_size) {
    const float* feat   = (const float*)d_in[0];
    const float* attn_l = (const float*)d_in[1];
    const float* attn_r = (const float*)d_in[2];
    const float* bias   = (const float*)d_in[3];
    const int*   src    = (const int*)d_in[4];
    // d_in[5] = dst: structurally repeat(arange(N), DEG); not needed.

    float* out = (float*)d_out;

    int threads1 = 256;
    int blocks1  = (NH + threads1 - 1) / threads1;
    precompute_dots<<<blocks1, threads1>>>(feat, attn_l, attn_r);

    gat_aggregate<<<N_NODES, 256>>>(feat, bias, src, out);
}

// round 2
// speedup vs baseline: 1.5675x; 1.5675x over previous
#include <cuda_runtime.h>
#include <math.h>

#define N_NODES 50000
#define H 8
#define D 32
#define DEG 16
#define HD (H * D)            // 256
#define NH (N_NODES * H)
#define NPB 4                 // nodes per block in aggregate kernel

// Scratch for precomputed attention dot-products (no cudaMalloc allowed).
__device__ float g_el[NH];
__device__ float g_er[NH];

// ---------------------------------------------------------------------------
// Kernel 1: el[n,h] = sum_d feat[n,h,d]*attn_l[h,d]; er likewise (one pass).
// ---------------------------------------------------------------------------
__global__ void precompute_dots(const float* __restrict__ feat,
                                const float* __restrict__ attn_l,
                                const float* __restrict__ attn_r) {
    __shared__ __align__(16) float sal[HD];
    __shared__ __align__(16) float sar[HD];
    int t = threadIdx.x;
    sal[t] = attn_l[t];
    sar[t] = attn_r[t];
    __syncthreads();

    int idx = blockIdx.x * blockDim.x + t;
    if (idx >= NH) return;
    int n = idx >> 3;       // node
    int h = idx & 7;        // head

    const float4* f  = reinterpret_cast<const float4*>(feat + (size_t)n * HD + h * D);
    const float4* al = reinterpret_cast<const float4*>(sal + h * D);
    const float4* ar = reinterpret_cast<const float4*>(sar + h * D);

    float sl = 0.f, sr = 0.f;
#pragma unroll
    for (int i = 0; i < D / 4; i++) {
        float4 v = f[i];
        float4 a = al[i];
        float4 b = ar[i];
        sl += v.x * a.x + v.y * a.y + v.z * a.z + v.w * a.w;
        sr += v.x * b.x + v.y * b.y + v.z * b.z + v.w * b.w;
    }
    g_el[idx] = sl;
    g_er[idx] = sr;
}

// ---------------------------------------------------------------------------
// Kernel 2: 256-thread block handles 4 nodes (64 threads / node).
// Edges of node n are [16n, 16n+16) since dst = repeat(arange(N), DEG).
//
// Per node (64 threads):
//   logits : lane u = h*8 + jj handles edges jj and jj+8 of head h,
//            softmax via shfl_xor over the 8-lane head group (2 vals/lane)
//   gather : lane u = h*8 + d4 accumulates float4 (h, d4*4..d4*4+3)
//            over 16 edges with LDG.128 (warp = 512B contiguous per edge)
// ---------------------------------------------------------------------------
__global__ __launch_bounds__(256) void gat_aggregate(
        const float* __restrict__ feat,
        const float* __restrict__ bias,
        const int*   __restrict__ src,
        float* __restrict__ out) {
    const int t    = threadIdx.x;
    const int n0   = blockIdx.x * NPB;
    const int node = t >> 6;     // 0..3
    const int u    = t & 63;
    const int h    = u >> 3;     // 0..7
    const int lo3  = u & 7;      // jj (phase B) / d4 (phase C)

    __shared__ int   s_src[NPB][DEG];
    __shared__ __align__(16) float s_a[NPB][H][DEG];

    // ---- Phase A: stage the 64 src indices -------------------------------
    if (t < NPB * DEG) {
        ((int*)s_src)[t] = src[n0 * DEG + t];
    }
    __syncthreads();

    // ---- Phase B: logits + shuffle softmax -------------------------------
    {
        const int n  = n0 + node;
        const float er_v = g_er[n * H + h];
        const int s0 = s_src[node][lo3];
        const int s1 = s_src[node][lo3 + 8];
        float e0 = g_el[s0 * H + h] + er_v;
        float e1 = g_el[s1 * H + h] + er_v;
        e0 = (e0 > 0.f) ? e0 : 0.2f * e0;
        e1 = (e1 > 0.f) ? e1 : 0.2f * e1;

        float m = fmaxf(e0, e1);
        m = fmaxf(m, __shfl_xor_sync(0xffffffffu, m, 4));
        m = fmaxf(m, __shfl_xor_sync(0xffffffffu, m, 2));
        m = fmaxf(m, __shfl_xor_sync(0xffffffffu, m, 1));

        float x0 = __expf(e0 - m);
        float x1 = __expf(e1 - m);
        float s  = x0 + x1;
        s += __shfl_xor_sync(0xffffffffu, s, 4);
        s += __shfl_xor_sync(0xffffffffu, s, 2);
        s += __shfl_xor_sync(0xffffffffu, s, 1);
        const float inv = 1.f / s;

        s_a[node][h][lo3]     = x0 * inv;
        s_a[node][h][lo3 + 8] = x1 * inv;
    }
    __syncthreads();

    // ---- Phase C: weighted float4 gather-aggregate ------------------------
    {
        // preload the 16 attention weights (4x LDS.128) and 16 src ids
        float av[DEG];
        {
            const float4* ap = reinterpret_cast<const float4*>(s_a[node][h]);
#pragma unroll
            for (int q = 0; q < 4; q++) {
                float4 v = ap[q];
                av[q * 4 + 0] = v.x; av[q * 4 + 1] = v.y;
                av[q * 4 + 2] = v.z; av[q * 4 + 3] = v.w;
            }
        }
        int sj[DEG];
        {
            const int4* sp = reinterpret_cast<const int4*>(s_src[node]);
#pragma unroll
            for (int q = 0; q < 4; q++) {
                int4 v = sp[q];
                sj[q * 4 + 0] = v.x; sj[q * 4 + 1] = v.y;
                sj[q * 4 + 2] = v.z; sj[q * 4 + 3] = v.w;
            }
        }

        const int off = h * D + lo3 * 4;   // float offset within a feat row
        float4 acc = *reinterpret_cast<const float4*>(bias + off);

#pragma unroll
        for (int j = 0; j < DEG; j++) {
            const float4 v = *reinterpret_cast<const float4*>(
                feat + (size_t)sj[j] * HD + off);
            const float a = av[j];
            acc.x += a * v.x;
            acc.y += a * v.y;
            acc.z += a * v.z;
            acc.w += a * v.w;
        }

        *reinterpret_cast<float4*>(out + (size_t)(n0 + node) * HD + off) = acc;
    }
}

// ---------------------------------------------------------------------------
extern "C" void kernel_launch(void* const* d_in, const int* in_sizes, int n_in,
                              void* d_out, int out_size) {
    const float* feat   = (const float*)d_in[0];
    const float* attn_l = (const float*)d_in[1];
    const float* attn_r = (const float*)d_in[2];
    const float* bias   = (const float*)d_in[3];
    const int*   src    = (const int*)d_in[4];
    // d_in[5] = dst: structurally repeat(arange(N), DEG); not needed.

    float* out = (float*)d_out;

    int threads1 = 256;
    int blocks1  = (NH + threads1 - 1) / threads1;
    precompute_dots<<<blocks1, threads1>>>(feat, attn_l, attn_r);

    gat_aggregate<<<N_NODES / NPB, 256>>>(feat, bias, src, out);
}